// round 7
// baseline (speedup 1.0000x reference)
#include <cuda_runtime.h>
#include <math_constants.h>

// Problem constants (from reference setup_inputs)
#define BATCH   8
#define NPTS    4096
#define NDIM    3

#define THREADS 128
#define PTS     4                    // x points per thread
#define XCHUNK  (THREADS * PTS)      // 512
#define NXCH    (NPTS / XCHUNK)      // 8
#define YCHUNK  32                   // y points per block tile (smem: ~17KB)
#define NYCH    (NPTS / YCHUNK)      // 128

#define NKEYS   (2 * BATCH * NPTS)   // 65536
#define RBLK    128                  // partial-reduce blocks
#define RTHR    256                  // partial-reduce threads/block
#define RPT     (NKEYS / (RBLK * RTHR))  // 2 keys per thread

// Min of s = (|p|^2 + |q|^2)/2 - p.q  (= d^2/2), stored as INVERTED monotone
// keys so the atomicMax identity is 0 (static zero-init; no init kernel).
// [0 .. B*N):      row mins  (x -> y)
// [B*N .. 2*B*N):  col mins  (y -> x)
__device__ unsigned int g_minkey[NKEYS];   // zero-initialized
__device__ float g_partial[RBLK];          // pure overwrite each replay

// Inverted monotone key: f1 < f2  <=>  key(f1) > key(f2); key(finite) > 0.
__device__ __forceinline__ unsigned int fkeyenc(float f) {
    unsigned int u = __float_as_uint(f);
    unsigned int m = ((unsigned int)((int)u >> 31)) | 0x80000000u;
    return ~(u ^ m);
}

__device__ __forceinline__ float fkeydec(unsigned int k) {
    unsigned int fk = ~k;
    unsigned int u = (fk & 0x80000000u) ? (fk ^ 0x80000000u) : ~fk;
    return __uint_as_float(u);
}

__global__ __launch_bounds__(THREADS, 8)
void chamfer_pairs_kernel(const float* __restrict__ x,
                          const float* __restrict__ y) {
    const int b = blockIdx.z;

    // q tile: (qx, qy, qz, hq) with hq = |q|^2/2 — one LDS.128 per j.
    __shared__ float4 sq[YCHUNK];
    // Per-thread column partials; row-major so the hot-loop STS is
    // conflict-free. 129-float row pitch keeps epilogue reads conflict-free.
    __shared__ float colpartial[YCHUNK][THREADS + 1];

    const int tid = threadIdx.x;

    const float* __restrict__ Qb =
        y + ((size_t)b * NPTS + (size_t)blockIdx.y * YCHUNK) * NDIM;
    if (tid < YCHUNK) {
        float qx = Qb[tid * 3 + 0];
        float qy = Qb[tid * 3 + 1];
        float qz = Qb[tid * 3 + 2];
        float hq = 0.5f * fmaf(qz, qz, fmaf(qy, qy, qx * qx));
        sq[tid] = make_float4(qx, qy, qz, hq);
    }
    __syncthreads();

    const int pbase = blockIdx.x * XCHUNK + tid;
    const float* __restrict__ Pb = x + (size_t)b * NPTS * NDIM;

    float px[PTS], py[PTS], pz[PTS], hp[PTS], rmn[PTS];
#pragma unroll
    for (int p = 0; p < PTS; p++) {
        int idx = pbase + p * THREADS;
        px[p] = Pb[idx * 3 + 0];
        py[p] = Pb[idx * 3 + 1];
        pz[p] = Pb[idx * 3 + 2];
        hp[p] = 0.5f * fmaf(pz[p], pz[p], fmaf(py[p], py[p], px[p] * px[p]));
        rmn[p] = CUDART_INF_F;
    }

    // Hot loop: per j, 4 unique pairs.
    //   s_p = hq - p.q        (3 FFMA; rows add hp after the min)
    //   col partial = min_p (s_p + hp_p)   (4 FADD + 3 FMNMX + 1 STS)
#pragma unroll 4
    for (int j = 0; j < YCHUNK; j++) {
        float4 q = sq[j];
        float s[PTS];
#pragma unroll
        for (int p = 0; p < PTS; p++) {
            float t = fmaf(-px[p], q.x, q.w);
            t = fmaf(-py[p], q.y, t);
            t = fmaf(-pz[p], q.z, t);
            s[p] = t;
            rmn[p] = fminf(rmn[p], t);
        }
        float c01 = fminf(s[0] + hp[0], s[1] + hp[1]);
        float c23 = fminf(s[2] + hp[2], s[3] + hp[3]);
        colpartial[j][tid] = fminf(c01, c23);
    }

    // Row partial mins -> global (inverted keys, atomicMax, result unused).
    unsigned int* grow = g_minkey + (size_t)b * NPTS;
#pragma unroll
    for (int p = 0; p < PTS; p++) {
        atomicMax(&grow[pbase + p * THREADS], fkeyenc(rmn[p] + hp[p]));
    }

    __syncthreads();

    // Column epilogue: 4 threads per column, each folds 32 partials, then a
    // 2-step shfl combine; lane group leader issues the global atomic.
    {
        const int j = tid >> 2;          // 0..31
        const int quarter = tid & 3;     // 0..3
        const float* cp = &colpartial[j][quarter * (THREADS / 4)];
        float m = CUDART_INF_F;
#pragma unroll 8
        for (int i = 0; i < THREADS / 4; i++) m = fminf(m, cp[i]);
        m = fminf(m, __shfl_xor_sync(0xFFFFFFFFu, m, 1));
        m = fminf(m, __shfl_xor_sync(0xFFFFFFFFu, m, 2));
        if (quarter == 0) {
            unsigned int* gcol = g_minkey + (size_t)BATCH * NPTS
                               + (size_t)b * NPTS + (size_t)blockIdx.y * YCHUNK;
            atomicMax(&gcol[j], fkeyenc(m));
        }
    }
}

// Stage 1: 128 blocks each sum a 512-key slice (sqrt of decoded d^2/2) and
// reset their slice of g_minkey for the next graph replay.
__global__ __launch_bounds__(RTHR)
void chamfer_partial_kernel() {
    __shared__ float ssum[RTHR];
    const int base = blockIdx.x * RTHR * RPT + threadIdx.x;
    float s = 0.0f;
#pragma unroll
    for (int r = 0; r < RPT; r++) {
        int i = base + r * RTHR;
        float halfd2 = fkeydec(g_minkey[i]);
        s += sqrtf(fmaxf(2.0f * halfd2, 0.0f));
        g_minkey[i] = 0u;   // exactly-once reset, race-free
    }
    ssum[threadIdx.x] = s;
    __syncthreads();
    for (int off = RTHR / 2; off >= 32; off >>= 1) {
        if (threadIdx.x < off) ssum[threadIdx.x] += ssum[threadIdx.x + off];
        __syncthreads();
    }
    if (threadIdx.x < 32) {
        float v = ssum[threadIdx.x];
        v += __shfl_xor_sync(0xFFFFFFFFu, v, 16);
        v += __shfl_xor_sync(0xFFFFFFFFu, v, 8);
        v += __shfl_xor_sync(0xFFFFFFFFu, v, 4);
        v += __shfl_xor_sync(0xFFFFFFFFu, v, 2);
        v += __shfl_xor_sync(0xFFFFFFFFu, v, 1);
        if (threadIdx.x == 0) g_partial[blockIdx.x] = v;
    }
}

// Stage 2: one warp folds the 128 block partials into the scalar output.
__global__ __launch_bounds__(32)
void chamfer_final_kernel(float* __restrict__ out) {
    float s = 0.0f;
#pragma unroll
    for (int r = 0; r < RBLK / 32; r++) s += g_partial[threadIdx.x + 32 * r];
    s += __shfl_xor_sync(0xFFFFFFFFu, s, 16);
    s += __shfl_xor_sync(0xFFFFFFFFu, s, 8);
    s += __shfl_xor_sync(0xFFFFFFFFu, s, 4);
    s += __shfl_xor_sync(0xFFFFFFFFu, s, 2);
    s += __shfl_xor_sync(0xFFFFFFFFu, s, 1);
    if (threadIdx.x == 0) out[0] = s / (float)(BATCH * NPTS);
}

extern "C" void kernel_launch(void* const* d_in, const int* in_sizes, int n_in,
                              void* d_out, int out_size) {
    const float* x = (const float*)d_in[0];
    const float* y = (const float*)d_in[1];
    float* out = (float*)d_out;

    dim3 grid(NXCH, NYCH, BATCH);   // 8 x 128 x 8 = 8192 blocks
    chamfer_pairs_kernel<<<grid, THREADS>>>(x, y);

    chamfer_partial_kernel<<<RBLK, RTHR>>>();
    chamfer_final_kernel<<<1, 32>>>(out);
}

// round 8
// speedup vs baseline: 1.1013x; 1.1013x over previous
#include <cuda_runtime.h>
#include <math_constants.h>

// Problem constants (from reference setup_inputs)
#define BATCH   8
#define NPTS    4096
#define NDIM    3

#define THREADS 128
#define PTS     8                    // x points per thread
#define XCHUNK  (THREADS * PTS)      // 1024
#define NXCH    (NPTS / XCHUNK)      // 4
#define YCHUNK  64                   // y points per block tile
#define NYCH    (NPTS / YCHUNK)      // 64

#define NKEYS   (2 * BATCH * NPTS)   // 65536
#define RBLK    128                  // partial-reduce blocks
#define RTHR    256                  // partial-reduce threads/block
#define RPT     (NKEYS / (RBLK * RTHR))  // 2 keys per thread

// Min of u = (|p|^2 + |q|^2)/2 - p.q  (= d^2/2), stored as INVERTED monotone
// keys so the atomicMax identity is 0 (static zero-init; no init kernel).
// [0 .. B*N):      row mins  (x -> y)
// [B*N .. 2*B*N):  col mins  (y -> x)
__device__ unsigned int g_minkey[NKEYS];   // zero-initialized
__device__ float g_partial[RBLK];          // pure overwrite each replay

// Inverted monotone key: f1 < f2  <=>  key(f1) > key(f2); key(finite) > 0.
__device__ __forceinline__ unsigned int fkeyenc(float f) {
    unsigned int u = __float_as_uint(f);
    unsigned int m = ((unsigned int)((int)u >> 31)) | 0x80000000u;
    return ~(u ^ m);
}

__device__ __forceinline__ float fkeydec(unsigned int k) {
    unsigned int fk = ~k;
    unsigned int u = (fk & 0x80000000u) ? (fk ^ 0x80000000u) : ~fk;
    return __uint_as_float(u);
}

__global__ __launch_bounds__(THREADS, 6)
void chamfer_pairs_kernel(const float* __restrict__ x,
                          const float* __restrict__ y) {
    const int b = blockIdx.z;

    // q tile: (qx, qy, qz, hq) with hq = |q|^2/2 — one LDS.128 per j.
    __shared__ float4 sq[YCHUNK];
    // Per-thread column partials; row-major so the hot-loop STS is
    // conflict-free. 129-float row pitch keeps epilogue reads conflict-free.
    __shared__ float colpartial[YCHUNK][THREADS + 1];

    const int tid = threadIdx.x;

    const float* __restrict__ Qb =
        y + ((size_t)b * NPTS + (size_t)blockIdx.y * YCHUNK) * NDIM;
    if (tid < YCHUNK) {
        float qx = Qb[tid * 3 + 0];
        float qy = Qb[tid * 3 + 1];
        float qz = Qb[tid * 3 + 2];
        float hq = 0.5f * fmaf(qz, qz, fmaf(qy, qy, qx * qx));
        sq[tid] = make_float4(qx, qy, qz, hq);
    }
    __syncthreads();

    const int pbase = blockIdx.x * XCHUNK + tid;
    const float* __restrict__ Pb = x + (size_t)b * NPTS * NDIM;

    // Negated components so the chain is pure FFMA: t = nx*qx + hp ...
    float nx[PTS], ny[PTS], nz[PTS], hp[PTS], rmn[PTS];
#pragma unroll
    for (int p = 0; p < PTS; p++) {
        int idx = pbase + p * THREADS;
        float px = Pb[idx * 3 + 0];
        float py = Pb[idx * 3 + 1];
        float pz = Pb[idx * 3 + 2];
        hp[p] = 0.5f * fmaf(pz, pz, fmaf(py, py, px * px));
        nx[p] = -px; ny[p] = -py; nz[p] = -pz;
        rmn[p] = CUDART_INF_F;
    }

    // Hot loop: per j, 8 unique pairs.
    //   u_p = hp_p + hq - p.q   (3 FFMA + 1 FADD = d^2/2 directly)
    //   row mins on u (hp folded in), col partial = tree-min of 8 u's.
#pragma unroll 2
    for (int j = 0; j < YCHUNK; j++) {
        float4 q = sq[j];
        float u[PTS];
#pragma unroll
        for (int p = 0; p < PTS; p++) {
            float t = fmaf(nx[p], q.x, hp[p]);
            t = fmaf(ny[p], q.y, t);
            t = fmaf(nz[p], q.z, t);
            u[p] = t + q.w;
            rmn[p] = fminf(rmn[p], u[p]);
        }
        float c0 = fminf(u[0], u[1]);
        float c1 = fminf(u[2], u[3]);
        float c2 = fminf(u[4], u[5]);
        float c3 = fminf(u[6], u[7]);
        colpartial[j][tid] = fminf(fminf(c0, c1), fminf(c2, c3));
    }

    // Row partial mins (already d^2/2) -> global.
    unsigned int* grow = g_minkey + (size_t)b * NPTS;
#pragma unroll
    for (int p = 0; p < PTS; p++) {
        atomicMax(&grow[pbase + p * THREADS], fkeyenc(rmn[p]));
    }

    __syncthreads();

    // Column epilogue: 2 threads per column fold 64 partials each, then one
    // shfl combine; even thread issues the global atomic.
    {
        const int j = tid >> 1;          // 0..63
        const int half = tid & 1;
        const float* cp = &colpartial[j][half * (THREADS / 2)];
        float m = CUDART_INF_F;
#pragma unroll 8
        for (int i = 0; i < THREADS / 2; i++) m = fminf(m, cp[i]);
        m = fminf(m, __shfl_xor_sync(0xFFFFFFFFu, m, 1));
        if (half == 0) {
            unsigned int* gcol = g_minkey + (size_t)BATCH * NPTS
                               + (size_t)b * NPTS + (size_t)blockIdx.y * YCHUNK;
            atomicMax(&gcol[j], fkeyenc(m));
        }
    }
}

// Stage 1: 128 blocks each sum a 512-key slice (sqrt of decoded d^2/2) and
// reset their slice of g_minkey for the next graph replay.
__global__ __launch_bounds__(RTHR)
void chamfer_partial_kernel() {
    __shared__ float ssum[RTHR];
    const int base = blockIdx.x * RTHR * RPT + threadIdx.x;
    float s = 0.0f;
#pragma unroll
    for (int r = 0; r < RPT; r++) {
        int i = base + r * RTHR;
        float halfd2 = fkeydec(g_minkey[i]);
        s += sqrtf(fmaxf(2.0f * halfd2, 0.0f));
        g_minkey[i] = 0u;   // exactly-once reset, race-free
    }
    ssum[threadIdx.x] = s;
    __syncthreads();
    for (int off = RTHR / 2; off >= 32; off >>= 1) {
        if (threadIdx.x < off) ssum[threadIdx.x] += ssum[threadIdx.x + off];
        __syncthreads();
    }
    if (threadIdx.x < 32) {
        float v = ssum[threadIdx.x];
        v += __shfl_xor_sync(0xFFFFFFFFu, v, 16);
        v += __shfl_xor_sync(0xFFFFFFFFu, v, 8);
        v += __shfl_xor_sync(0xFFFFFFFFu, v, 4);
        v += __shfl_xor_sync(0xFFFFFFFFu, v, 2);
        v += __shfl_xor_sync(0xFFFFFFFFu, v, 1);
        if (threadIdx.x == 0) g_partial[blockIdx.x] = v;
    }
}

// Stage 2: one warp folds the 128 block partials into the scalar output.
__global__ __launch_bounds__(32)
void chamfer_final_kernel(float* __restrict__ out) {
    float s = 0.0f;
#pragma unroll
    for (int r = 0; r < RBLK / 32; r++) s += g_partial[threadIdx.x + 32 * r];
    s += __shfl_xor_sync(0xFFFFFFFFu, s, 16);
    s += __shfl_xor_sync(0xFFFFFFFFu, s, 8);
    s += __shfl_xor_sync(0xFFFFFFFFu, s, 4);
    s += __shfl_xor_sync(0xFFFFFFFFu, s, 2);
    s += __shfl_xor_sync(0xFFFFFFFFu, s, 1);
    if (threadIdx.x == 0) out[0] = s / (float)(BATCH * NPTS);
}

extern "C" void kernel_launch(void* const* d_in, const int* in_sizes, int n_in,
                              void* d_out, int out_size) {
    const float* x = (const float*)d_in[0];
    const float* y = (const float*)d_in[1];
    float* out = (float*)d_out;

    dim3 grid(NXCH, NYCH, BATCH);   // 4 x 64 x 8 = 2048 blocks
    chamfer_pairs_kernel<<<grid, THREADS>>>(x, y);

    chamfer_partial_kernel<<<RBLK, RTHR>>>();
    chamfer_final_kernel<<<1, 32>>>(out);
}

// round 9
// speedup vs baseline: 1.1325x; 1.0283x over previous
#include <cuda_runtime.h>
#include <math_constants.h>

// Problem constants (from reference setup_inputs)
#define BATCH   8
#define NPTS    4096
#define NDIM    3

#define THREADS 128
#define PTS     8                    // x points per thread
#define XCHUNK  (THREADS * PTS)      // 1024
#define NXCH    (NPTS / XCHUNK)      // 4
#define YCHUNK  64                   // y points per block tile
#define NYCH    (NPTS / YCHUNK)      // 64

#define NKEYS   (2 * BATCH * NPTS)   // 65536
#define RBLK    128                  // partial-reduce blocks
#define RTHR    256                  // partial-reduce threads/block
#define RPT     (NKEYS / (RBLK * RTHR))  // 2 keys per thread

// Min of u = (|p|^2 + |q|^2)/2 - p.q  (= d^2/2), stored as INVERTED monotone
// keys so the atomicMax identity is 0 (static zero-init; no init kernel).
// [0 .. B*N):      row mins  (x -> y)
// [B*N .. 2*B*N):  col mins  (y -> x)
__device__ unsigned int g_minkey[NKEYS];   // zero-initialized
__device__ float g_partial[RBLK];          // pure overwrite each replay

// Inverted monotone key: f1 < f2  <=>  key(f1) > key(f2); key(finite) > 0.
__device__ __forceinline__ unsigned int fkeyenc(float f) {
    unsigned int u = __float_as_uint(f);
    unsigned int m = ((unsigned int)((int)u >> 31)) | 0x80000000u;
    return ~(u ^ m);
}

__device__ __forceinline__ float fkeydec(unsigned int k) {
    unsigned int fk = ~k;
    unsigned int u = (fk & 0x80000000u) ? (fk ^ 0x80000000u) : ~fk;
    return __uint_as_float(u);
}

__global__ __launch_bounds__(THREADS, 6)
void chamfer_pairs_kernel(const float* __restrict__ x,
                          const float* __restrict__ y) {
    const int b = blockIdx.z;

    // q tile: (qx, qy, qz, hq) with hq = |q|^2/2 — one LDS.128 per j.
    __shared__ float4 sq[YCHUNK];
    // Per-thread column partials; row-major so the hot-loop STS is
    // conflict-free. 129-float row pitch keeps epilogue reads conflict-free.
    __shared__ float colpartial[YCHUNK][THREADS + 1];

    const int tid = threadIdx.x;

    const float* __restrict__ Qb =
        y + ((size_t)b * NPTS + (size_t)blockIdx.y * YCHUNK) * NDIM;
    if (tid < YCHUNK) {
        float qx = Qb[tid * 3 + 0];
        float qy = Qb[tid * 3 + 1];
        float qz = Qb[tid * 3 + 2];
        float hq = 0.5f * fmaf(qz, qz, fmaf(qy, qy, qx * qx));
        sq[tid] = make_float4(qx, qy, qz, hq);
    }
    __syncthreads();

    const int pbase = blockIdx.x * XCHUNK + tid;
    const float* __restrict__ Pb = x + (size_t)b * NPTS * NDIM;

    // Negated components so the chain is pure FFMA seeded by hq:
    //   t = hq - p.q  (rows min t directly; hp added once at the atomic)
    float nx[PTS], ny[PTS], nz[PTS], hp[PTS], rmn[PTS];
#pragma unroll
    for (int p = 0; p < PTS; p++) {
        int idx = pbase + p * THREADS;
        float px = Pb[idx * 3 + 0];
        float py = Pb[idx * 3 + 1];
        float pz = Pb[idx * 3 + 2];
        hp[p] = 0.5f * fmaf(pz, pz, fmaf(py, py, px * px));
        nx[p] = -px; ny[p] = -py; nz[p] = -pz;
        rmn[p] = CUDART_INF_F;
    }

    // Hot loop: per j, 8 unique pairs.
    //   t_p = hq - p.q            (3 FFMA)
    //   rows:  rmn_p = min(rmn_p, t_p)          (FMNMX, no FADD on this path)
    //   cols:  partial = min_p (t_p + hp_p)     (8 FADD + 7 FMNMX tree)
#pragma unroll 4
    for (int j = 0; j < YCHUNK; j++) {
        float4 q = sq[j];
        float u[PTS];
#pragma unroll
        for (int p = 0; p < PTS; p++) {
            float t = fmaf(nx[p], q.x, q.w);
            t = fmaf(ny[p], q.y, t);
            t = fmaf(nz[p], q.z, t);
            rmn[p] = fminf(rmn[p], t);
            u[p] = t + hp[p];
        }
        float c0 = fminf(u[0], u[1]);
        float c1 = fminf(u[2], u[3]);
        float c2 = fminf(u[4], u[5]);
        float c3 = fminf(u[6], u[7]);
        colpartial[j][tid] = fminf(fminf(c0, c1), fminf(c2, c3));
    }

    // Row partial mins -> global (add hp once here; inverted keys, atomicMax).
    unsigned int* grow = g_minkey + (size_t)b * NPTS;
#pragma unroll
    for (int p = 0; p < PTS; p++) {
        atomicMax(&grow[pbase + p * THREADS], fkeyenc(rmn[p] + hp[p]));
    }

    __syncthreads();

    // Column epilogue: 2 threads per column fold 64 partials each, then one
    // shfl combine; even thread issues the global atomic.
    {
        const int j = tid >> 1;          // 0..63
        const int half = tid & 1;
        const float* cp = &colpartial[j][half * (THREADS / 2)];
        float m = CUDART_INF_F;
#pragma unroll 8
        for (int i = 0; i < THREADS / 2; i++) m = fminf(m, cp[i]);
        m = fminf(m, __shfl_xor_sync(0xFFFFFFFFu, m, 1));
        if (half == 0) {
            unsigned int* gcol = g_minkey + (size_t)BATCH * NPTS
                               + (size_t)b * NPTS + (size_t)blockIdx.y * YCHUNK;
            atomicMax(&gcol[j], fkeyenc(m));
        }
    }
}

// Stage 1: 128 blocks each sum a 512-key slice (sqrt of decoded d^2/2) and
// reset their slice of g_minkey for the next graph replay.
__global__ __launch_bounds__(RTHR)
void chamfer_partial_kernel() {
    __shared__ float ssum[RTHR];
    const int base = blockIdx.x * RTHR * RPT + threadIdx.x;
    float s = 0.0f;
#pragma unroll
    for (int r = 0; r < RPT; r++) {
        int i = base + r * RTHR;
        float halfd2 = fkeydec(g_minkey[i]);
        s += sqrtf(fmaxf(2.0f * halfd2, 0.0f));
        g_minkey[i] = 0u;   // exactly-once reset, race-free
    }
    ssum[threadIdx.x] = s;
    __syncthreads();
    for (int off = RTHR / 2; off >= 32; off >>= 1) {
        if (threadIdx.x < off) ssum[threadIdx.x] += ssum[threadIdx.x + off];
        __syncthreads();
    }
    if (threadIdx.x < 32) {
        float v = ssum[threadIdx.x];
        v += __shfl_xor_sync(0xFFFFFFFFu, v, 16);
        v += __shfl_xor_sync(0xFFFFFFFFu, v, 8);
        v += __shfl_xor_sync(0xFFFFFFFFu, v, 4);
        v += __shfl_xor_sync(0xFFFFFFFFu, v, 2);
        v += __shfl_xor_sync(0xFFFFFFFFu, v, 1);
        if (threadIdx.x == 0) g_partial[blockIdx.x] = v;
    }
}

// Stage 2: one warp folds the 128 block partials into the scalar output.
__global__ __launch_bounds__(32)
void chamfer_final_kernel(float* __restrict__ out) {
    float s = 0.0f;
#pragma unroll
    for (int r = 0; r < RBLK / 32; r++) s += g_partial[threadIdx.x + 32 * r];
    s += __shfl_xor_sync(0xFFFFFFFFu, s, 16);
    s += __shfl_xor_sync(0xFFFFFFFFu, s, 8);
    s += __shfl_xor_sync(0xFFFFFFFFu, s, 4);
    s += __shfl_xor_sync(0xFFFFFFFFu, s, 2);
    s += __shfl_xor_sync(0xFFFFFFFFu, s, 1);
    if (threadIdx.x == 0) out[0] = s / (float)(BATCH * NPTS);
}

extern "C" void kernel_launch(void* const* d_in, const int* in_sizes, int n_in,
                              void* d_out, int out_size) {
    const float* x = (const float*)d_in[0];
    const float* y = (const float*)d_in[1];
    float* out = (float*)d_out;

    dim3 grid(NXCH, NYCH, BATCH);   // 4 x 64 x 8 = 2048 blocks
    chamfer_pairs_kernel<<<grid, THREADS>>>(x, y);

    chamfer_partial_kernel<<<RBLK, RTHR>>>();
    chamfer_final_kernel<<<1, 32>>>(out);
}